// round 1
// baseline (speedup 1.0000x reference)
#include <cuda_runtime.h>
#include <math.h>

// Problem constants (fixed by the dataset: N=100000, P=256, K=64, R=16)
#define PDIM   256
#define RNK    16
#define BM     64      // rows (points) per block
#define PB     16      // p-panel depth per smem stage
#define BN     256     // columns (= 16 components) per chunk
#define XPITCH 68      // padded pitch for Xs (conflict-free, 16B aligned)
#define DPITCH 68

// Scratch (no allocations allowed): W is [p][K*R] = [256][1024]
__device__ float g_W[PDIM * 1024];
__device__ float g_cK[64];
__device__ float g_partials[4096];

typedef unsigned long long u64;

__device__ __forceinline__ u64 pack2(float a, float b) {
    u64 r; asm("mov.b64 %0, {%1, %2};" : "=l"(r) : "f"(a), "f"(b)); return r;
}
__device__ __forceinline__ void unpack2(u64 v, float &a, float &b) {
    asm("mov.b64 {%0, %1}, %2;" : "=f"(a), "=f"(b) : "l"(v));
}
__device__ __forceinline__ void fma2(u64 &d, u64 a, u64 b) {
    // packed f32x2 FMA: 2 FMAs per lane per instruction (FFMA2 in SASS)
    asm("fma.rn.f32x2 %0, %1, %2, %0;" : "+l"(d) : "l"(a), "l"(b));
}

// ---------------------------------------------------------------------------
// Kernel A: per-component prep.
//   D_k = I + M_k^T M_k ; Cholesky D=LL^T ; W_k = M_k L^{-T} ; c_k constants.
// One block per component k, 256 threads.
// ---------------------------------------------------------------------------
__global__ void prep_kernel(const float *__restrict__ M,
                            const float *__restrict__ pi, int K) {
    const int k = blockIdx.x;
    const int t = threadIdx.x;
    __shared__ float Ms[PDIM * RNK];   // 16 KB: M_k, row-major [p][r]
    __shared__ float Dm[RNK * RNK];
    __shared__ float Lm[RNK * RNK];

    for (int i = t; i < PDIM * RNK; i += 256)
        Ms[i] = M[(size_t)k * PDIM * RNK + i];
    __syncthreads();

    // G(i,j) = sum_p Ms[p][i]*Ms[p][j]; 256 threads = 16x16 entries
    {
        const int i = t >> 4, j = t & 15;
        float s = 0.f;
        for (int p = 0; p < PDIM; p++)
            s += Ms[p * RNK + i] * Ms[p * RNK + j];
        Dm[i * RNK + j] = s + (i == j ? 1.0f : 0.0f);
    }
    __syncthreads();

    if (t == 0) {
        // Cholesky (serial, 16x16 -- trivial)
        for (int j = 0; j < RNK; j++) {
            float d = Dm[j * RNK + j];
            for (int q = 0; q < j; q++) d -= Lm[j * RNK + q] * Lm[j * RNK + q];
            float lj = sqrtf(d);
            Lm[j * RNK + j] = lj;
            float inv = 1.0f / lj;
            for (int i = j + 1; i < RNK; i++) {
                float v = Dm[i * RNK + j];
                for (int q = 0; q < j; q++) v -= Lm[i * RNK + q] * Lm[j * RNK + q];
                Lm[i * RNK + j] = v * inv;
            }
        }
        float logdet = 0.f;
        for (int j = 0; j < RNK; j++) logdet += logf(Lm[j * RNK + j]);
        logdet *= 2.0f;
        // log_softmax(pi)[k]
        float mx = -1e30f;
        for (int q = 0; q < K; q++) mx = fmaxf(mx, pi[q]);
        float ss = 0.f;
        for (int q = 0; q < K; q++) ss += expf(pi[q] - mx);
        float lse = mx + logf(ss);
        double half_p = 0.5 * (double)PDIM;
        double logSA = lgamma(half_p) - log(2.0) - half_p * log(3.14159265358979323846);
        g_cK[k] = (float)logSA - 0.5f * logdet + (pi[k] - lse);
    }
    __syncthreads();

    // Solve row p of W:  w L^T = m  =>  w_j = (m_j - sum_{i<j} L[j][i] w_i)/L[j][j]
    {
        const int p = t;   // 256 threads == PDIM rows
        float w[RNK];
#pragma unroll
        for (int j = 0; j < RNK; j++) {
            float v = Ms[p * RNK + j];
#pragma unroll
            for (int i = 0; i < RNK; i++)
                if (i < j) v -= Lm[j * RNK + i] * w[i];
            w[j] = v / Lm[j * RNK + j];
        }
        const int KR = K * RNK;
#pragma unroll
        for (int j = 0; j < RNK; j++)
            g_W[p * KR + k * RNK + j] = w[j];
    }
}

// ---------------------------------------------------------------------------
// Kernel B: fused GEMM + squared-norm + logsumexp.
//   Y = X[BM,256] @ W[256, KR], quad = per-16-col squared sums,
//   density = c_k - (P/2) * log1p(-quad), rowval = logsumexp_k(density),
//   partial[b] = sum of rowvals in the block's tile.
// Thread map: tr = t&15 (4 rows each -> 64 rows), tk = t>>4 (one component).
// Accumulators packed f32x2 along adjacent r pairs of the same component.
// ---------------------------------------------------------------------------
__global__ __launch_bounds__(256) void gemm_kernel(const float *__restrict__ X,
                                                   int N, int KR) {
    extern __shared__ float sm[];
    float *Xs  = sm;                        // [256][XPITCH]
    float *Ws  = sm + PDIM * XPITCH;        // [PB][BN]
    float *dens = Ws + PB * BN;             // [BM][DPITCH]

    const int t = threadIdx.x;
    const int tr = t & 15;
    const int tk = t >> 4;
    const int row0 = blockIdx.x * BM;

    // Stage X tile (transposed): Xs[p][n], conflict-free writes (pitch 68)
    for (int idx = t; idx < BM * PDIM; idx += 256) {
        int n = idx >> 8;        // idx / 256
        int p = idx & 255;       // idx % 256
        int gn = row0 + n;
        Xs[p * XPITCH + n] = (gn < N) ? X[(size_t)gn * PDIM + p] : 0.0f;
    }

    u64 acc[4][8];
    const int nchunk = KR / BN;     // 4
    const float half_p = 0.5f * (float)PDIM;

    for (int chunk = 0; chunk < nchunk; chunk++) {
#pragma unroll
        for (int u = 0; u < 4; u++)
#pragma unroll
            for (int j = 0; j < 8; j++) acc[u][j] = 0ULL;

        for (int pc = 0; pc < PDIM; pc += PB) {
            __syncthreads();   // previous Ws consumers done (also fences Xs stage)
            // stage W panel: [PB][BN] floats, vectorized + coalesced
            for (int idx = t; idx < PB * BN / 4; idx += 256) {
                int pp = idx >> 6;       // / (BN/4)
                int c4 = idx & 63;
                reinterpret_cast<float4 *>(Ws)[pp * (BN / 4) + c4] =
                    *reinterpret_cast<const float4 *>(
                        &g_W[(size_t)(pc + pp) * KR + chunk * BN + c4 * 4]);
            }
            __syncthreads();

#pragma unroll
            for (int pp = 0; pp < PB; pp++) {
                float4 x4 = *reinterpret_cast<const float4 *>(
                    &Xs[(pc + pp) * XPITCH + 4 * tr]);
                u64 xp0 = pack2(x4.x, x4.x);
                u64 xp1 = pack2(x4.y, x4.y);
                u64 xp2 = pack2(x4.z, x4.z);
                u64 xp3 = pack2(x4.w, x4.w);
                const u64 *wrow = reinterpret_cast<const u64 *>(
                    &Ws[pp * BN + tk * RNK]);
#pragma unroll
                for (int j = 0; j < 8; j++) {
                    u64 w2 = wrow[j];
                    fma2(acc[0][j], xp0, w2);
                    fma2(acc[1][j], xp1, w2);
                    fma2(acc[2][j], xp2, w2);
                    fma2(acc[3][j], xp3, w2);
                }
            }
        }

        // chunk epilogue: quad -> density for component kglob
        const int kglob = chunk * 16 + tk;
        const float ck = g_cK[kglob];
#pragma unroll
        for (int u = 0; u < 4; u++) {
            float q = 0.f;
#pragma unroll
            for (int j = 0; j < 8; j++) {
                float lo, hi;
                unpack2(acc[u][j], lo, hi);
                q += lo * lo + hi * hi;
            }
            float dv = ck - half_p * log1pf(-q);
            dens[(4 * tr + u) * DPITCH + kglob] = dv;
        }
    }
    __syncthreads();

    // per-row logsumexp over all K components, then fixed-order block sum
    __shared__ float rowvals[BM];
    const int Kc = KR / RNK;
    if (t < BM) {
        int gn = row0 + t;
        float out = 0.f;
        if (gn < N) {
            float m = -1e30f;
            for (int k = 0; k < Kc; k++) m = fmaxf(m, dens[t * DPITCH + k]);
            float s = 0.f;
            for (int k = 0; k < Kc; k++) s += expf(dens[t * DPITCH + k] - m);
            out = m + logf(s);
        }
        rowvals[t] = out;
    }
    __syncthreads();
    if (t == 0) {
        float s = 0.f;
        for (int i = 0; i < BM; i++) s += rowvals[i];
        g_partials[blockIdx.x] = s;
    }
}

// ---------------------------------------------------------------------------
// Kernel C: deterministic final reduction (fixed order, double accumulate)
// ---------------------------------------------------------------------------
__global__ void reduce_kernel(int nb, float *__restrict__ out) {
    __shared__ double sd[256];
    double s = 0.0;
    for (int i = threadIdx.x; i < nb; i += 256) s += (double)g_partials[i];
    sd[threadIdx.x] = s;
    __syncthreads();
    for (int off = 128; off > 0; off >>= 1) {
        if (threadIdx.x < off) sd[threadIdx.x] += sd[threadIdx.x + off];
        __syncthreads();
    }
    if (threadIdx.x == 0) out[0] = (float)sd[0];
}

// ---------------------------------------------------------------------------
extern "C" void kernel_launch(void *const *d_in, const int *in_sizes, int n_in,
                              void *d_out, int out_size) {
    const float *X  = (const float *)d_in[0];
    const float *M  = (const float *)d_in[1];
    const float *pi = (const float *)d_in[2];
    const int K  = in_sizes[2];
    const int N  = in_sizes[0] / PDIM;
    const int KR = K * RNK;

    prep_kernel<<<K, 256>>>(M, pi, K);

    const int nb = (N + BM - 1) / BM;
    const size_t smem =
        (size_t)(PDIM * XPITCH + PB * BN + BM * DPITCH) * sizeof(float);
    cudaFuncSetAttribute(gemm_kernel,
                         cudaFuncAttributeMaxDynamicSharedMemorySize,
                         (int)smem);
    gemm_kernel<<<nb, 256, smem>>>(X, N, KR);

    reduce_kernel<<<1, 256>>>(nb, (float *)d_out);
}

// round 4
// speedup vs baseline: 2.0947x; 2.0947x over previous
#include <cuda_runtime.h>
#include <cuda_bf16.h>
#include <math.h>
#include <stdint.h>

// Problem constants (fixed: N=100000, P=256, K=64, R=16)
#define PDIM   256
#define RNK    16
#define KCOMP  64
#define BM     128            // rows per CTA
#define NCHUNK 8              // 8 chunks x 128 cols = 1024 = K*R
#define NPANEL 4              // K split: 4 panels x 64
#define NITER  (NCHUNK * NPANEL)

// dynamic smem map (bytes)
#define SM_AHI   0u           // A hi: [128 rows][256 k] bf16, swizzled chunks (64KB)
#define SM_ALO   65536u
#define SM_B     131072u      // 2 stages x (hi 16KB + lo 16KB)
#define SM_TOTAL 196608u

// ------------- scratch (no allocations allowed) -------------
// W blocks [chunk][panel]: 32KB = hi[col 128][k 64] + lo, ldmatrix-swizzled.
__device__ __align__(128) unsigned char g_Wb[NITER * 32768];
__device__ float g_cK[KCOMP];
__device__ float g_partials[1024];

// ------------- PTX helpers (all plain sm_90-level PTX, no 'a' features) ----
__device__ __forceinline__ uint32_t smem_u32(const void *p) {
    uint32_t a;
    asm("{ .reg .u64 t; cvta.to.shared.u64 t, %1; cvt.u32.u64 %0, t; }"
        : "=r"(a) : "l"(p));
    return a;
}
__device__ __forceinline__ void mbar_init(uint32_t mbar, uint32_t cnt) {
    asm volatile("mbarrier.init.shared.b64 [%0], %1;" :: "r"(mbar), "r"(cnt) : "memory");
}
__device__ __forceinline__ void mbar_expect_tx(uint32_t mbar, uint32_t bytes) {
    asm volatile("mbarrier.arrive.expect_tx.shared.b64 _, [%0], %1;"
                 :: "r"(mbar), "r"(bytes) : "memory");
}
__device__ __forceinline__ void mbar_wait(uint32_t mbar, uint32_t parity) {
    asm volatile(
        "{\n\t.reg .pred P1;\n\t"
        "WL%=:\n\t"
        "mbarrier.try_wait.parity.acquire.cta.shared::cta.b64 P1, [%0], %1, 0x989680;\n\t"
        "@P1 bra.uni WD%=;\n\t"
        "bra.uni WL%=;\n\t"
        "WD%=:\n\t}"
        :: "r"(mbar), "r"(parity) : "memory");
}
__device__ __forceinline__ void bulk_g2s(uint32_t dst, const void *src,
                                         uint32_t bytes, uint32_t mbar) {
    asm volatile(
        "cp.async.bulk.shared::cluster.global.mbarrier::complete_tx::bytes "
        "[%0], [%1], %2, [%3];"
        :: "r"(dst), "l"(src), "r"(bytes), "r"(mbar) : "memory");
}
__device__ __forceinline__ void ldsm4(uint32_t *r, uint32_t addr) {
    asm volatile("ldmatrix.sync.aligned.m8n8.x4.shared.b16 {%0,%1,%2,%3}, [%4];"
                 : "=r"(r[0]), "=r"(r[1]), "=r"(r[2]), "=r"(r[3]) : "r"(addr));
}
__device__ __forceinline__ void mma16816(float *c, const uint32_t *a,
                                         uint32_t b0, uint32_t b1) {
    asm volatile(
        "mma.sync.aligned.m16n8k16.row.col.f32.bf16.bf16.f32 "
        "{%0,%1,%2,%3}, {%4,%5,%6,%7}, {%8,%9}, {%0,%1,%2,%3};"
        : "+f"(c[0]), "+f"(c[1]), "+f"(c[2]), "+f"(c[3])
        : "r"(a[0]), "r"(a[1]), "r"(a[2]), "r"(a[3]), "r"(b0), "r"(b1));
}

// ---------------------------------------------------------------------------
// prep: D = I + M^T M, Cholesky, W = M L^{-T}, constants; W written as bf16
// hi/lo into ldmatrix-swizzled gmem blocks [chunk][panel].
// ---------------------------------------------------------------------------
__global__ void prep_kernel(const float *__restrict__ M,
                            const float *__restrict__ pi, int K) {
    const int k = blockIdx.x;
    const int t = threadIdx.x;
    __shared__ float Ms[PDIM * RNK];
    __shared__ float Dm[RNK * RNK];
    __shared__ float Lm[RNK * RNK];

    for (int i = t; i < PDIM * RNK; i += 256)
        Ms[i] = M[(size_t)k * PDIM * RNK + i];
    __syncthreads();

    {
        const int i = t >> 4, j = t & 15;
        float s = 0.f;
        for (int p = 0; p < PDIM; p++)
            s += Ms[p * RNK + i] * Ms[p * RNK + j];
        Dm[i * RNK + j] = s + (i == j ? 1.0f : 0.0f);
    }
    __syncthreads();

    if (t == 0) {
        for (int j = 0; j < RNK; j++) {
            float d = Dm[j * RNK + j];
            for (int q = 0; q < j; q++) d -= Lm[j * RNK + q] * Lm[j * RNK + q];
            float lj = sqrtf(d);
            Lm[j * RNK + j] = lj;
            float inv = 1.0f / lj;
            for (int i = j + 1; i < RNK; i++) {
                float v = Dm[i * RNK + j];
                for (int q = 0; q < j; q++) v -= Lm[i * RNK + q] * Lm[j * RNK + q];
                Lm[i * RNK + j] = v * inv;
            }
        }
        float logdet = 0.f;
        for (int j = 0; j < RNK; j++) logdet += logf(Lm[j * RNK + j]);
        logdet *= 2.0f;
        float mx = -1e30f;
        for (int q = 0; q < K; q++) mx = fmaxf(mx, pi[q]);
        float ss = 0.f;
        for (int q = 0; q < K; q++) ss += expf(pi[q] - mx);
        float lse = mx + logf(ss);
        double half_p = 0.5 * (double)PDIM;
        double logSA = lgamma(half_p) - log(2.0) - half_p * log(3.14159265358979323846);
        g_cK[k] = (float)logSA - 0.5f * logdet + (pi[k] - lse);
    }
    __syncthreads();

    // Row p: solve w L^T = m, write hi/lo into swizzled block layout.
    {
        const int p = t;        // global k-index 0..255
        float w[RNK];
#pragma unroll
        for (int j = 0; j < RNK; j++) {
            float v = Ms[p * RNK + j];
#pragma unroll
            for (int i = 0; i < RNK; i++)
                if (i < j) v -= Lm[j * RNK + i] * w[i];
            w[j] = v / Lm[j * RNK + j];
        }
        const int chunk = k >> 3;       // 8 comps per 128-col chunk
        const int panel = p >> 6;       // K panel (64 each)
        const int kk    = p & 63;
        const int ck    = kk >> 3;      // 16B chunk within panel row (0..7)
        const int byt   = (kk & 7) * 2;
#pragma unroll
        for (int j = 0; j < RNK; j++) {
            int col = (k & 7) * RNK + j;              // 0..127 within chunk
            uint32_t off = (uint32_t)(chunk * NPANEL + panel) * 32768u
                         + (uint32_t)col * 128u
                         + (uint32_t)((ck ^ (col & 7)) * 16 + byt);
            __nv_bfloat16 hi = __float2bfloat16(w[j]);
            __nv_bfloat16 lo = __float2bfloat16(w[j] - __bfloat162float(hi));
            *(__nv_bfloat16 *)(g_Wb + off)          = hi;
            *(__nv_bfloat16 *)(g_Wb + off + 16384u) = lo;
        }
    }
}

// ---------------------------------------------------------------------------
// Fused GEMM (mma.sync bf16, 3-term hi/lo split) + density + online LSE.
// 8 warps: wr = wid&3 -> 32-row band, wn = wid>>2 -> 64-col half.
// ---------------------------------------------------------------------------
__global__ __launch_bounds__(256) void gemm_kernel(const float *__restrict__ X,
                                                   int N) {
    extern __shared__ unsigned char smc[];
    const uint32_t sb = smem_u32(smc);
    const int t = threadIdx.x;
    const int wid = t >> 5;
    const int lane = t & 31;
    const int wr = wid & 3;
    const int wn = wid >> 2;
    const int tid4 = lane & 3;
    const int group = lane >> 2;
    const int row0 = blockIdx.x * BM;

    __shared__ float cKs[KCOMP];
    __shared__ uint64_t barsS[2];
    __shared__ float mergeM[4][32], mergeS[4][32];
    __shared__ float wsumS[4];
    const uint32_t bar0 = smem_u32(&barsS[0]);
    const uint32_t bar1 = smem_u32(&barsS[1]);

    if (t == 0) { mbar_init(bar0, 1); mbar_init(bar1, 1); }
    if (t < KCOMP) cKs[t] = g_cK[t];

    // ---- stage A: X fp32 -> bf16 hi/lo, swizzled 16B chunks ----
    for (int i = t; i < BM * 32; i += 256) {
        const int row = i >> 5;
        const int c   = i & 31;               // 16B chunk along k (8 bf16)
        float4 v0 = make_float4(0.f, 0.f, 0.f, 0.f), v1 = v0;
        if (row0 + row < N) {
            const float *src = &X[(size_t)(row0 + row) * PDIM + c * 8];
            v0 = *reinterpret_cast<const float4 *>(src);
            v1 = *reinterpret_cast<const float4 *>(src + 4);
        }
        float f[8] = {v0.x, v0.y, v0.z, v0.w, v1.x, v1.y, v1.z, v1.w};
        uint32_t hw[4], lw[4];
#pragma unroll
        for (int j = 0; j < 4; j++) {
            __nv_bfloat16 h0 = __float2bfloat16(f[2 * j]);
            __nv_bfloat16 h1 = __float2bfloat16(f[2 * j + 1]);
            __nv_bfloat16 l0 = __float2bfloat16(f[2 * j] - __bfloat162float(h0));
            __nv_bfloat16 l1 = __float2bfloat16(f[2 * j + 1] - __bfloat162float(h1));
            hw[j] = ((uint32_t)__bfloat16_as_ushort(h1) << 16) | __bfloat16_as_ushort(h0);
            lw[j] = ((uint32_t)__bfloat16_as_ushort(l1) << 16) | __bfloat16_as_ushort(l0);
        }
        const uint32_t cswz = (uint32_t)((c & ~7) | ((c & 7) ^ (row & 7)));
        uint4 *dhi = (uint4 *)(smc + SM_AHI + row * 512u + cswz * 16u);
        uint4 *dlo = (uint4 *)(smc + SM_ALO + row * 512u + cswz * 16u);
        *dhi = make_uint4(hw[0], hw[1], hw[2], hw[3]);
        *dlo = make_uint4(lw[0], lw[1], lw[2], lw[3]);
    }
    asm volatile("fence.proxy.async.shared::cta;" ::: "memory");
    __syncthreads();

    // prologue: prefetch panels 0,1
    if (t == 0) {
        mbar_expect_tx(bar0, 32768);
        bulk_g2s(sb + SM_B, g_Wb, 32768, bar0);
        mbar_expect_tx(bar1, 32768);
        bulk_g2s(sb + SM_B + 32768u, g_Wb + 32768, 32768, bar1);
    }

    float lm = -1e30f, ls = 0.f;         // per-lane online logsumexp
    int ph0 = 0, ph1 = 0;
    float acc[2][8][4];

    for (int chunk = 0; chunk < NCHUNK; chunk++) {
#pragma unroll
        for (int m2 = 0; m2 < 2; m2++)
#pragma unroll
            for (int nt = 0; nt < 8; nt++)
#pragma unroll
                for (int j = 0; j < 4; j++) acc[m2][nt][j] = 0.f;

        for (int panel = 0; panel < NPANEL; panel++) {
            const int iter = chunk * NPANEL + panel;
            const int stg = iter & 1;
            if (stg == 0) { mbar_wait(bar0, (uint32_t)ph0); ph0 ^= 1; }
            else          { mbar_wait(bar1, (uint32_t)ph1); ph1 ^= 1; }

            const uint32_t bB = sb + SM_B + (uint32_t)stg * 32768u;
#pragma unroll
            for (int ks = 0; ks < 4; ks++) {
                uint32_t ah[2][4], al[2][4];
#pragma unroll
                for (int m2 = 0; m2 < 2; m2++) {
                    const int rowl = wr * 32 + m2 * 16 + (lane & 15);
                    const int c = panel * 8 + ks * 2 + (lane >> 4);
                    const uint32_t cswz =
                        (uint32_t)((c & ~7) | ((c & 7) ^ (rowl & 7)));
                    const uint32_t ad = sb + SM_AHI + rowl * 512u + cswz * 16u;
                    ldsm4(ah[m2], ad);
                    ldsm4(al[m2], ad + 65536u);
                }
                uint32_t bh[4][4], bl[4][4];
#pragma unroll
                for (int ng = 0; ng < 4; ng++) {
                    const int coll = wn * 64 + ng * 16 + (lane & 15);
                    const int ck = ks * 2 + (lane >> 4);
                    const uint32_t bd =
                        bB + coll * 128u + (uint32_t)((ck ^ (coll & 7)) * 16);
                    ldsm4(bh[ng], bd);
                    ldsm4(bl[ng], bd + 16384u);
                }
#pragma unroll
                for (int m2 = 0; m2 < 2; m2++)
#pragma unroll
                    for (int ng = 0; ng < 4; ng++)
#pragma unroll
                        for (int h = 0; h < 2; h++) {
                            float *cc = acc[m2][ng * 2 + h];
                            mma16816(cc, ah[m2], bh[ng][h], bh[ng][2 + h]);
                            mma16816(cc, ah[m2], bl[ng][h], bl[ng][2 + h]);
                            mma16816(cc, al[m2], bh[ng][h], bh[ng][2 + h]);
                        }
            }
            __syncthreads();
            if (t == 0 && iter + 2 < NITER) {
                const uint32_t bar = stg ? bar1 : bar0;
                mbar_expect_tx(bar, 32768);
                bulk_g2s(sb + SM_B + (uint32_t)stg * 32768u,
                         g_Wb + (size_t)(iter + 2) * 32768u, 32768, bar);
            }
        }

        // ---- chunk epilogue: quads -> density -> online LSE ----
#pragma unroll
        for (int c4 = 0; c4 < 4; c4++) {
            float qsel = 0.f;
#pragma unroll
            for (int m2 = 0; m2 < 2; m2++)
#pragma unroll
                for (int h = 0; h < 2; h++) {
                    float q = 0.f;
#pragma unroll
                    for (int dn = 0; dn < 2; dn++) {
                        const float *cc = acc[m2][2 * c4 + dn];
                        q += cc[2 * h] * cc[2 * h] + cc[2 * h + 1] * cc[2 * h + 1];
                    }
                    q += __shfl_xor_sync(0xffffffffu, q, 1);
                    q += __shfl_xor_sync(0xffffffffu, q, 2);
                    if (tid4 == m2 * 2 + h) qsel = q;
                }
            const int comp = chunk * 8 + wn * 4 + c4;
            const float dens = cKs[comp] - 128.0f * log1pf(-qsel);
            const float nm = fmaxf(lm, dens);
            ls = ls * expf(lm - nm) + expf(dens - nm);
            lm = nm;
        }
    }

    // ---- merge the two wn halves, per-row value, deterministic block sum ----
    if (wn == 1) { mergeM[wr][lane] = lm; mergeS[wr][lane] = ls; }
    __syncthreads();
    if (wn == 0) {
        const float m2v = mergeM[wr][lane], s2v = mergeS[wr][lane];
        const float nm = fmaxf(lm, m2v);
        const float s = ls * expf(lm - nm) + s2v * expf(m2v - nm);
        const int rowl = wr * 32 + (tid4 >> 1) * 16 + (tid4 & 1) * 8 + group;
        float rv = (row0 + rowl < N) ? (nm + logf(s)) : 0.f;
#pragma unroll
        for (int off = 16; off > 0; off >>= 1)
            rv += __shfl_down_sync(0xffffffffu, rv, off);
        if (lane == 0) wsumS[wr] = rv;
    }
    __syncthreads();
    if (t == 0)
        g_partials[blockIdx.x] = (wsumS[0] + wsumS[1]) + (wsumS[2] + wsumS[3]);
}

// ---------------------------------------------------------------------------
__global__ void reduce_kernel(int nb, float *__restrict__ out) {
    __shared__ double sd[256];
    double s = 0.0;
    for (int i = threadIdx.x; i < nb; i += 256) s += (double)g_partials[i];
    sd[threadIdx.x] = s;
    __syncthreads();
    for (int off = 128; off > 0; off >>= 1) {
        if (threadIdx.x < off) sd[threadIdx.x] += sd[threadIdx.x + off];
        __syncthreads();
    }
    if (threadIdx.x == 0) out[0] = (float)sd[0];
}

// ---------------------------------------------------------------------------
extern "C" void kernel_launch(void *const *d_in, const int *in_sizes, int n_in,
                              void *d_out, int out_size) {
    const float *X  = (const float *)d_in[0];
    const float *M  = (const float *)d_in[1];
    const float *pi = (const float *)d_in[2];
    const int K = in_sizes[2];
    const int N = in_sizes[0] / PDIM;

    prep_kernel<<<K, 256>>>(M, pi, K);

    const int nb = (N + BM - 1) / BM;
    cudaFuncSetAttribute(gemm_kernel,
                         cudaFuncAttributeMaxDynamicSharedMemorySize,
                         (int)SM_TOTAL);
    gemm_kernel<<<nb, 256, SM_TOTAL>>>(X, N);

    reduce_kernel<<<1, 256>>>(nb, (float *)d_out);
}